// round 5
// baseline (speedup 1.0000x reference)
#include <cuda_runtime.h>
#include <math.h>

#define QLEN   1024
#define BSZ    4
#define DMODEL 1024
#define NHEAD  16
#define GHEADS 2
#define DHEAD  64
#define QKD    128
#define QKVOUT 1280
#define MROWS  4096
#define SCALE  0.125f
#define LN_EPS 1e-5f

// ---------------- scratch (device globals; no allocations allowed) ----------
__device__ float g_wheads[MROWS * QKVOUT];            // 4096 x 1280
__device__ float g_rk[QLEN * QKD];                    // 1024 x 128
__device__ float g_AC[BSZ * GHEADS * QLEN * QLEN];    // [bg][i][j]
__device__ float g_BD[BSZ * GHEADS * QLEN * QLEN];    // [bg][i][j] (pre-shift)
__device__ float g_avec[MROWS * DMODEL];              // attn_vec
__device__ float g_x[MROWS * DMODEL];                 // residual pre-LN

// ---------------- generic NT SGEMM: C[m,n] = sum_k A[m,k]*B[n,k] (+D) -------
// BM=BN=128, BK=16, 256 threads, 8x8 microtile. All dims assumed divisible.
template<int RESID>
__global__ void __launch_bounds__(256) sgemm_nt(
    const float* __restrict__ A, int lda,
    const float* __restrict__ B, int ldb,
    const float* __restrict__ D,
    float* __restrict__ C, int N_, int K)
{
    __shared__ float As[16][132];
    __shared__ float Bs[16][132];
    const int bx = blockIdx.x, by = blockIdx.y;
    const int t  = threadIdx.x;
    const int tx = t & 15, ty = t >> 4;
    float acc[8][8];
    #pragma unroll
    for (int i = 0; i < 8; i++)
        #pragma unroll
        for (int j = 0; j < 8; j++) acc[i][j] = 0.f;

    const float* Ab = A + (size_t)(by * 128) * lda;
    const float* Bb = B + (size_t)(bx * 128) * ldb;
    const int lrow = t >> 2;          // 0..63
    const int lk4  = (t & 3) * 4;     // 0,4,8,12

    for (int k0 = 0; k0 < K; k0 += 16) {
        #pragma unroll
        for (int rr = 0; rr < 2; rr++) {
            int m = lrow + rr * 64;
            float4 a  = *(const float4*)(Ab + (size_t)m * lda + k0 + lk4);
            As[lk4 + 0][m] = a.x;  As[lk4 + 1][m] = a.y;
            As[lk4 + 2][m] = a.z;  As[lk4 + 3][m] = a.w;
            float4 bv = *(const float4*)(Bb + (size_t)m * ldb + k0 + lk4);
            Bs[lk4 + 0][m] = bv.x; Bs[lk4 + 1][m] = bv.y;
            Bs[lk4 + 2][m] = bv.z; Bs[lk4 + 3][m] = bv.w;
        }
        __syncthreads();
        #pragma unroll
        for (int kk = 0; kk < 16; kk++) {
            float ar[8], br[8];
            #pragma unroll
            for (int u = 0; u < 8; u++) ar[u] = As[kk][ty * 8 + u];
            #pragma unroll
            for (int u = 0; u < 8; u++) br[u] = Bs[kk][tx * 8 + u];
            #pragma unroll
            for (int i = 0; i < 8; i++)
                #pragma unroll
                for (int j = 0; j < 8; j++) acc[i][j] += ar[i] * br[j];
        }
        __syncthreads();
    }
    const int mbase = by * 128 + ty * 8;
    const int nbase = bx * 128 + tx * 8;
    #pragma unroll
    for (int i = 0; i < 8; i++) {
        size_t roff = (size_t)(mbase + i) * N_ + nbase;
        #pragma unroll
        for (int j0 = 0; j0 < 8; j0 += 4) {
            float4 o;
            o.x = acc[i][j0 + 0]; o.y = acc[i][j0 + 1];
            o.z = acc[i][j0 + 2]; o.w = acc[i][j0 + 3];
            if (RESID) {
                float4 d = *(const float4*)(D + roff + j0);
                o.x += d.x; o.y += d.y; o.z += d.z; o.w += d.w;
            }
            *(float4*)(C + roff + j0) = o;
        }
    }
}

// ---------------- AC / BD batched GEMM (K=64) -------------------------------
// mode 0: C=AC : A[m,d]=Q[m,b,g,d]+rwb[g,d], B[n,d]=K[n,b,g,d]
// mode 1: C=BD : A[m,d]=Q[m,b,g,d]+rrb[g,d], B[n,d]=rk[n,g,d]
__global__ void __launch_bounds__(256) acbd_kernel(
    const float* __restrict__ wheads, const float* __restrict__ rk,
    const float* __restrict__ bias,   // [GHEADS][DHEAD]
    float* __restrict__ Cbase, int mode)
{
    __shared__ float As[16][132];
    __shared__ float Bs[16][132];
    const int bg = blockIdx.z;
    const int b = bg >> 1, g = bg & 1;
    const int bx = blockIdx.x, by = blockIdx.y;
    const int t  = threadIdx.x;
    const int tx = t & 15, ty = t >> 4;

    const float* Aoff = wheads + b * QKVOUT + g * 64;
    const float* Boff = mode ? (rk + g * 64)
                             : (wheads + b * QKVOUT + QKD + g * 64);
    const int lda = BSZ * QKVOUT;
    const int ldb = mode ? QKD : (BSZ * QKVOUT);
    const float* bb = bias + g * 64;

    float acc[8][8];
    #pragma unroll
    for (int i = 0; i < 8; i++)
        #pragma unroll
        for (int j = 0; j < 8; j++) acc[i][j] = 0.f;

    const int lrow = t >> 2;
    const int lk4  = (t & 3) * 4;

    for (int k0 = 0; k0 < 64; k0 += 16) {
        float4 bias4 = *(const float4*)(bb + k0 + lk4);
        #pragma unroll
        for (int rr = 0; rr < 2; rr++) {
            int m = lrow + rr * 64;
            int gm = by * 128 + m;
            float4 a = *(const float4*)(Aoff + (size_t)gm * lda + k0 + lk4);
            As[lk4 + 0][m] = a.x + bias4.x; As[lk4 + 1][m] = a.y + bias4.y;
            As[lk4 + 2][m] = a.z + bias4.z; As[lk4 + 3][m] = a.w + bias4.w;
            int gn = bx * 128 + m;
            float4 bv = *(const float4*)(Boff + (size_t)gn * ldb + k0 + lk4);
            Bs[lk4 + 0][m] = bv.x; Bs[lk4 + 1][m] = bv.y;
            Bs[lk4 + 2][m] = bv.z; Bs[lk4 + 3][m] = bv.w;
        }
        __syncthreads();
        #pragma unroll
        for (int kk = 0; kk < 16; kk++) {
            float ar[8], br[8];
            #pragma unroll
            for (int u = 0; u < 8; u++) ar[u] = As[kk][ty * 8 + u];
            #pragma unroll
            for (int u = 0; u < 8; u++) br[u] = Bs[kk][tx * 8 + u];
            #pragma unroll
            for (int i = 0; i < 8; i++)
                #pragma unroll
                for (int j = 0; j < 8; j++) acc[i][j] += ar[i] * br[j];
        }
        __syncthreads();
    }
    float* C = Cbase + (size_t)bg * QLEN * QLEN;
    const int mbase = by * 128 + ty * 8;
    const int nbase = bx * 128 + tx * 8;
    #pragma unroll
    for (int i = 0; i < 8; i++) {
        size_t roff = (size_t)(mbase + i) * QLEN + nbase;
        #pragma unroll
        for (int j0 = 0; j0 < 8; j0 += 4) {
            float4 o;
            o.x = acc[i][j0 + 0]; o.y = acc[i][j0 + 1];
            o.z = acc[i][j0 + 2]; o.w = acc[i][j0 + 3];
            *(float4*)(C + roff + j0) = o;
        }
    }
}

// ---------------- fused score + rel_shift + mask + softmax + PV -------------
// grid: (64 = b*16+h, 32 = i-tile of 32 rows), 512 threads.
// dynamic smem: S[32][1024] fp32 (131072 B); static: invs[32]
__global__ void __launch_bounds__(512) attn_kernel(
    const float* __restrict__ AC, const float* __restrict__ BD,
    const float* __restrict__ masks, const float* __restrict__ mproj,
    const float* __restrict__ wheads, float* __restrict__ avec)
{
    extern __shared__ float S[];            // 32 * 1024
    __shared__ float invs[32];

    const int bh = blockIdx.x;
    const int b  = bh >> 4, h = bh & 15;
    const int g  = h >> 3;
    const int bg = b * 2 + g;
    const int i0 = blockIdx.y * 32;
    const int t  = threadIdx.x;
    const int warp = t >> 5, lane = t & 31;

    const float mp0 = mproj[0 * NHEAD + h];
    const float mp1 = mproj[1 * NHEAD + h];
    const float mp2 = mproj[2 * NHEAD + h];

    // ---- Phase A: scores + softmax (each warp owns 2 rows) ----
    #pragma unroll
    for (int rr = 0; rr < 2; rr++) {
        const int r = warp * 2 + rr;
        const int i = i0 + r;
        const float* acrow = AC + ((size_t)bg * QLEN + i) * QLEN;
        const float* bdbase = BD + (size_t)bg * QLEN * QLEN;
        float mx = -1e30f;
        for (int j = lane; j < QLEN; j += 32) {
            float ac = acrow[j];
            unsigned s  = (unsigned)(i + 1) * 1024u + (unsigned)j;
            unsigned i2 = s / 1025u;
            unsigned j2 = s - i2 * 1025u;
            float bd = (j2 == 0u) ? 0.f : bdbase[(size_t)i2 * QLEN + (j2 - 1u)];
            const float* mrow = masks + ((size_t)i * QLEN + j) * 3;
            float mw = mrow[0] * mp0 + mrow[1] * mp1 + mrow[2] * mp2;
            float v = (ac + bd) * SCALE * mw;
            S[r * QLEN + j] = v;
            mx = fmaxf(mx, v);
        }
        #pragma unroll
        for (int o = 16; o > 0; o >>= 1)
            mx = fmaxf(mx, __shfl_xor_sync(0xffffffffu, mx, o));
        float sum = 0.f;
        for (int j = lane; j < QLEN; j += 32) {
            float e = __expf(S[r * QLEN + j] - mx);
            S[r * QLEN + j] = e;
            sum += e;
        }
        #pragma unroll
        for (int o = 16; o > 0; o >>= 1)
            sum += __shfl_xor_sync(0xffffffffu, sum, o);
        if (lane == 0) invs[r] = 1.f / sum;
    }
    __syncthreads();

    // ---- Phase B: out[r, d] = invs[r] * sum_j P[r,j] * V[j,b,h,d] ----
    // t -> r = t/16 (0..31), d4 = t%16 (float4 column)
    const int r  = t >> 4;
    const int d4 = t & 15;
    const int i  = i0 + r;
    const float* Vbase = wheads + (size_t)b * QKVOUT + 2 * QKD + h * 64 + d4 * 4;
    const float* Sr = S + r * QLEN;
    float4 acc = make_float4(0.f, 0.f, 0.f, 0.f);
    #pragma unroll 4
    for (int j = 0; j < QLEN; j++) {
        float p = Sr[j];
        float4 v = *(const float4*)(Vbase + (size_t)j * (BSZ * QKVOUT));
        acc.x += p * v.x; acc.y += p * v.y;
        acc.z += p * v.z; acc.w += p * v.w;
    }
    float is = invs[r];
    acc.x *= is; acc.y *= is; acc.z *= is; acc.w *= is;
    *(float4*)(avec + ((size_t)(i * BSZ + b) * NHEAD + h) * 64 + d4 * 4) = acc;
}

// ---------------- LayerNorm over rows of g_x --------------------------------
__global__ void __launch_bounds__(256) ln_kernel(
    const float* __restrict__ X, const float* __restrict__ gamma,
    const float* __restrict__ beta, float* __restrict__ out)
{
    const int row = blockIdx.x;
    const int t = threadIdx.x;
    const float4* x4 = (const float4*)(X + (size_t)row * DMODEL);
    float4 v = x4[t];
    float s  = v.x + v.y + v.z + v.w;
    float sq = v.x * v.x + v.y * v.y + v.z * v.z + v.w * v.w;
    #pragma unroll
    for (int o = 16; o > 0; o >>= 1) {
        s  += __shfl_xor_sync(0xffffffffu, s,  o);
        sq += __shfl_xor_sync(0xffffffffu, sq, o);
    }
    __shared__ float ssum[8], ssq[8];
    __shared__ float smu, srstd;
    if ((t & 31) == 0) { ssum[t >> 5] = s; ssq[t >> 5] = sq; }
    __syncthreads();
    if (t == 0) {
        float ts = 0.f, tq = 0.f;
        #pragma unroll
        for (int k = 0; k < 8; k++) { ts += ssum[k]; tq += ssq[k]; }
        float mu = ts * (1.f / DMODEL);
        float var = tq * (1.f / DMODEL) - mu * mu;
        smu = mu;
        srstd = rsqrtf(var + LN_EPS);
    }
    __syncthreads();
    float mu = smu, rstd = srstd;
    float4 gm = ((const float4*)gamma)[t];
    float4 bt = ((const float4*)beta)[t];
    float4 o;
    o.x = (v.x - mu) * rstd * gm.x + bt.x;
    o.y = (v.y - mu) * rstd * gm.y + bt.y;
    o.z = (v.z - mu) * rstd * gm.z + bt.z;
    o.w = (v.w - mu) * rstd * gm.w + bt.w;
    ((float4*)(out + (size_t)row * DMODEL))[t] = o;
}

// ---------------- launch ----------------------------------------------------
extern "C" void kernel_launch(void* const* d_in, const int* in_sizes, int n_in,
                              void* d_out, int out_size)
{
    const float* w     = (const float*)d_in[0];   // [1024,4,1024]
    const float* r     = (const float*)d_in[1];   // [1024,1024]
    const float* rwb   = (const float*)d_in[2];   // [2,64]
    const float* rrb   = (const float*)d_in[3];   // [2,64]
    const float* masks = (const float*)d_in[4];   // [1024,1024,3]
    const float* Wqkv  = (const float*)d_in[5];   // [1280,1024]
    const float* Wr    = (const float*)d_in[6];   // [128,1024]
    const float* mproj = (const float*)d_in[7];   // [3,16]
    const float* Wo    = (const float*)d_in[8];   // [1024,1024]
    const float* gamma = (const float*)d_in[9];   // [1024]
    const float* beta  = (const float*)d_in[10];  // [1024]
    float* out = (float*)d_out;

    float *wheads, *rkp, *acp, *bdp, *avp, *xp;
    cudaGetSymbolAddress((void**)&wheads, g_wheads);
    cudaGetSymbolAddress((void**)&rkp,    g_rk);
    cudaGetSymbolAddress((void**)&acp,    g_AC);
    cudaGetSymbolAddress((void**)&bdp,    g_BD);
    cudaGetSymbolAddress((void**)&avp,    g_avec);
    cudaGetSymbolAddress((void**)&xp,     g_x);

    cudaFuncSetAttribute(attn_kernel,
                         cudaFuncAttributeMaxDynamicSharedMemorySize,
                         32 * QLEN * (int)sizeof(float));

    // 1) w_heads = w @ W_qkv^T : [4096,1280]
    sgemm_nt<0><<<dim3(QKVOUT / 128, MROWS / 128), 256>>>(
        w, DMODEL, Wqkv, DMODEL, nullptr, wheads, QKVOUT, DMODEL);

    // 2) r_head_k = r @ W_r^T : [1024,128]
    sgemm_nt<0><<<dim3(QKD / 128, QLEN / 128), 256>>>(
        r, DMODEL, Wr, DMODEL, nullptr, rkp, QKD, DMODEL);

    // 3) AC, BD (pre-shift)
    acbd_kernel<<<dim3(8, 8, BSZ * GHEADS), 256>>>(wheads, rkp, rwb, acp, 0);
    acbd_kernel<<<dim3(8, 8, BSZ * GHEADS), 256>>>(wheads, rkp, rrb, bdp, 1);

    // 4) fused rel_shift + mask + softmax + P@V
    attn_kernel<<<dim3(64, 32), 512, 32 * QLEN * sizeof(float)>>>(
        acp, bdp, masks, mproj, wheads, avp);

    // 5) x = attn_vec @ W_o^T + w
    sgemm_nt<1><<<dim3(DMODEL / 128, MROWS / 128), 256>>>(
        avp, DMODEL, Wo, DMODEL, w, xp, DMODEL, DMODEL);

    // 6) LayerNorm -> out
    ln_kernel<<<MROWS, 256>>>(xp, gamma, beta, out);
}

// round 8
// speedup vs baseline: 1.2223x; 1.2223x over previous
#include <cuda_runtime.h>
#include <cuda_bf16.h>
#include <math.h>
#include <stdint.h>

#define QLEN   1024
#define BSZ    4
#define DMODEL 1024
#define NHEAD  16
#define GHEADS 2
#define DHEAD  64
#define QKD    128
#define QKVOUT 1280
#define MROWS  4096
#define SCALE  0.125f
#define LN_EPS 1e-5f

// ---------------- scratch (device globals; no allocations allowed) ----------
__device__ float g_wheads[MROWS * QKVOUT];            // 4096 x 1280
__device__ float g_rk[QLEN * QKD];                    // 1024 x 128
__device__ float g_AC[BSZ * GHEADS * QLEN * QLEN];    // [bg][i][j]
__device__ float g_BD[BSZ * GHEADS * QLEN * QLEN];    // [bg][i][j] (pre-shift)
__device__ float g_avec[MROWS * DMODEL];              // attn_vec
__device__ float g_x[MROWS * DMODEL];                 // residual pre-LN

// bf16 hi/lo operand buffers (reused across the three GEMMs; stream-ordered)
__device__ __nv_bfloat16 g_bfA_hi[MROWS * DMODEL];    // 8 MB
__device__ __nv_bfloat16 g_bfA_lo[MROWS * DMODEL];
__device__ __nv_bfloat16 g_bfB_hi[QKVOUT * DMODEL];   // 2.5 MB
__device__ __nv_bfloat16 g_bfB_lo[QKVOUT * DMODEL];

// ---------------- helpers ----------------------------------------------------
__device__ __forceinline__ uint32_t smem_u32(const void* p) {
    uint32_t a;
    asm("{ .reg .u64 t; cvta.to.shared.u64 t, %1; cvt.u32.u64 %0, t; }"
        : "=r"(a) : "l"(p));
    return a;
}
__device__ __forceinline__ void ldm4(uint32_t* r, uint32_t addr) {
    asm volatile("ldmatrix.sync.aligned.m8n8.x4.shared.b16 {%0,%1,%2,%3}, [%4];"
                 : "=r"(r[0]), "=r"(r[1]), "=r"(r[2]), "=r"(r[3]) : "r"(addr));
}
__device__ __forceinline__ void mma16816(float* c, const uint32_t* a,
                                         uint32_t b0, uint32_t b1) {
    asm volatile(
        "mma.sync.aligned.m16n8k16.row.col.f32.bf16.bf16.f32 "
        "{%0,%1,%2,%3}, {%4,%5,%6,%7}, {%8,%9}, {%0,%1,%2,%3};"
        : "+f"(c[0]), "+f"(c[1]), "+f"(c[2]), "+f"(c[3])
        : "r"(a[0]), "r"(a[1]), "r"(a[2]), "r"(a[3]), "r"(b0), "r"(b1));
}

// ---------------- fp32 -> bf16 hi/lo split ----------------------------------
__global__ void __launch_bounds__(256) cvt_split(
    const float* __restrict__ x, __nv_bfloat16* __restrict__ hi,
    __nv_bfloat16* __restrict__ lo, int n)
{
    int i = (blockIdx.x * 256 + threadIdx.x) * 4;
    if (i >= n) return;
    float4 v = *(const float4*)(x + i);
    union { __nv_bfloat16 b[4]; uint2 u; } H, L;
    H.b[0] = __float2bfloat16_rn(v.x);
    H.b[1] = __float2bfloat16_rn(v.y);
    H.b[2] = __float2bfloat16_rn(v.z);
    H.b[3] = __float2bfloat16_rn(v.w);
    L.b[0] = __float2bfloat16_rn(v.x - __bfloat162float(H.b[0]));
    L.b[1] = __float2bfloat16_rn(v.y - __bfloat162float(H.b[1]));
    L.b[2] = __float2bfloat16_rn(v.z - __bfloat162float(H.b[2]));
    L.b[3] = __float2bfloat16_rn(v.w - __bfloat162float(H.b[3]));
    *(uint2*)(hi + i) = H.u;
    *(uint2*)(lo + i) = L.u;
}

// ---------------- HMMA split-bf16 NT GEMM -----------------------------------
// C[m,n] = sum_k A[m,k]*B[n,k] (+Dres), fp32 via Ahi*Bhi + Ahi*Blo + Alo*Bhi.
// BM=BN=128, BK=32 bf16. 256 threads = 8 warps (2m x 4n), warp tile 64x32.
// Smem tiles K-major, row stride 40 bf16 (80 B) for conflict-free ldmatrix.
#define LDSB 40

__global__ void __launch_bounds__(256) mma_gemm(
    const __nv_bfloat16* __restrict__ Ahi, const __nv_bfloat16* __restrict__ Alo,
    const __nv_bfloat16* __restrict__ Bhi, const __nv_bfloat16* __restrict__ Blo,
    const float* __restrict__ Dres, float* __restrict__ C, int N_, int K)
{
    __shared__ __nv_bfloat16 sAh[128 * LDSB];
    __shared__ __nv_bfloat16 sAl[128 * LDSB];
    __shared__ __nv_bfloat16 sBh[128 * LDSB];
    __shared__ __nv_bfloat16 sBl[128 * LDSB];

    const int t = threadIdx.x;
    const int warp = t >> 5, lane = t & 31;
    const int wm = warp >> 2, wn = warp & 3;     // 2 x 4 warp grid
    const int m0 = blockIdx.y * 128, n0 = blockIdx.x * 128;

    float acc[4][4][4];
    #pragma unroll
    for (int i = 0; i < 4; i++)
        #pragma unroll
        for (int j = 0; j < 4; j++)
            #pragma unroll
            for (int u = 0; u < 4; u++) acc[i][j][u] = 0.f;

    // global load mapping: 256 threads, each loads 2 rows x 8 bf16 per tile
    const int lrow = t >> 2;          // 0..63
    const int lseg = (t & 3) * 8;     // 0,8,16,24  (bf16 offset inside BK=32)

    const __nv_bfloat16* pAh = Ahi + (size_t)m0 * K;
    const __nv_bfloat16* pAl = Alo + (size_t)m0 * K;
    const __nv_bfloat16* pBh = Bhi + (size_t)n0 * K;
    const __nv_bfloat16* pBl = Blo + (size_t)n0 * K;

    const uint32_t sAh_b = smem_u32(sAh), sAl_b = smem_u32(sAl);
    const uint32_t sBh_b = smem_u32(sBh), sBl_b = smem_u32(sBl);

    // ldmatrix per-lane byte offsets (within tile; add mf/np*1280 and k-step*32)
    const uint32_t a_lane =
        ((uint32_t)(wm * 64 + (lane & 15)) * LDSB + (lane >> 4) * 8) * 2;
    const uint32_t b_lane =
        ((uint32_t)(wn * 32 + (lane & 7) + (lane >> 4) * 8) * LDSB +
         ((lane >> 3) & 1) * 8) * 2;

    for (int k0 = 0; k0 < K; k0 += 32) {
        #pragma unroll
        for (int rr = 0; rr < 2; rr++) {
            const int row = lrow + rr * 64;
            const size_t go = (size_t)row * K + k0 + lseg;
            const uint32_t so = (uint32_t)row * LDSB + lseg;
            *(uint4*)&sAh[so] = *(const uint4*)(pAh + go);
            *(uint4*)&sAl[so] = *(const uint4*)(pAl + go);
            *(uint4*)&sBh[so] = *(const uint4*)(pBh + go);
            *(uint4*)&sBl[so] = *(const uint4*)(pBl + go);
        }
        __syncthreads();

        #pragma unroll
        for (int s = 0; s < 2; s++) {
            const uint32_t ko = s * 32;   // 16 bf16 = 32 bytes
            uint32_t ah[4][4], al[4][4], bh[2][4], bl[2][4];
            #pragma unroll
            for (int mf = 0; mf < 4; mf++) {
                ldm4(ah[mf], sAh_b + a_lane + mf * 1280 + ko);
                ldm4(al[mf], sAl_b + a_lane + mf * 1280 + ko);
            }
            #pragma unroll
            for (int np = 0; np < 2; np++) {
                ldm4(bh[np], sBh_b + b_lane + np * 1280 + ko);
                ldm4(bl[np], sBl_b + b_lane + np * 1280 + ko);
            }
            #pragma unroll
            for (int mf = 0; mf < 4; mf++) {
                #pragma unroll
                for (int nf = 0; nf < 4; nf++) {
                    const int np = nf >> 1, h = (nf & 1) * 2;
                    mma16816(acc[mf][nf], ah[mf], bh[np][h], bh[np][h + 1]);
                    mma16816(acc[mf][nf], ah[mf], bl[np][h], bl[np][h + 1]);
                    mma16816(acc[mf][nf], al[mf], bh[np][h], bh[np][h + 1]);
                }
            }
        }
        __syncthreads();
    }

    // epilogue: c0,c1 -> (row, col..col+1); c2,c3 -> (row+8, ...)
    const int crow0 = m0 + wm * 64 + (lane >> 2);
    const int ccol0 = n0 + wn * 32 + (lane & 3) * 2;
    #pragma unroll
    for (int mf = 0; mf < 4; mf++) {
        #pragma unroll
        for (int nf = 0; nf < 4; nf++) {
            const int gr = crow0 + mf * 16;
            const int gc = ccol0 + nf * 8;
            float2 v0 = make_float2(acc[mf][nf][0], acc[mf][nf][1]);
            float2 v1 = make_float2(acc[mf][nf][2], acc[mf][nf][3]);
            if (Dres) {
                float2 d0 = *(const float2*)(Dres + (size_t)gr * N_ + gc);
                float2 d1 = *(const float2*)(Dres + (size_t)(gr + 8) * N_ + gc);
                v0.x += d0.x; v0.y += d0.y;
                v1.x += d1.x; v1.y += d1.y;
            }
            *(float2*)(C + (size_t)gr * N_ + gc) = v0;
            *(float2*)(C + (size_t)(gr + 8) * N_ + gc) = v1;
        }
    }
}

// ---------------- AC / BD batched GEMM (K=64, fp32 FFMA) --------------------
__global__ void __launch_bounds__(256) acbd_kernel(
    const float* __restrict__ wheads, const float* __restrict__ rk,
    const float* __restrict__ bias,   // [GHEADS][DHEAD]
    float* __restrict__ Cbase, int mode)
{
    __shared__ float As[16][132];
    __shared__ float Bs[16][132];
    const int bg = blockIdx.z;
    const int b = bg >> 1, g = bg & 1;
    const int bx = blockIdx.x, by = blockIdx.y;
    const int t  = threadIdx.x;
    const int tx = t & 15, ty = t >> 4;

    const float* Aoff = wheads + b * QKVOUT + g * 64;
    const float* Boff = mode ? (rk + g * 64)
                             : (wheads + b * QKVOUT + QKD + g * 64);
    const int lda = BSZ * QKVOUT;
    const int ldb = mode ? QKD : (BSZ * QKVOUT);
    const float* bb = bias + g * 64;

    float acc[8][8];
    #pragma unroll
    for (int i = 0; i < 8; i++)
        #pragma unroll
        for (int j = 0; j < 8; j++) acc[i][j] = 0.f;

    const int lrow = t >> 2;
    const int lk4  = (t & 3) * 4;

    for (int k0 = 0; k0 < 64; k0 += 16) {
        float4 bias4 = *(const float4*)(bb + k0 + lk4);
        #pragma unroll
        for (int rr = 0; rr < 2; rr++) {
            int m = lrow + rr * 64;
            int gm = by * 128 + m;
            float4 a = *(const float4*)(Aoff + (size_t)gm * lda + k0 + lk4);
            As[lk4 + 0][m] = a.x + bias4.x; As[lk4 + 1][m] = a.y + bias4.y;
            As[lk4 + 2][m] = a.z + bias4.z; As[lk4 + 3][m] = a.w + bias4.w;
            int gn = bx * 128 + m;
            float4 bv = *(const float4*)(Boff + (size_t)gn * ldb + k0 + lk4);
            Bs[lk4 + 0][m] = bv.x; Bs[lk4 + 1][m] = bv.y;
            Bs[lk4 + 2][m] = bv.z; Bs[lk4 + 3][m] = bv.w;
        }
        __syncthreads();
        #pragma unroll
        for (int kk = 0; kk < 16; kk++) {
            float ar[8], br[8];
            #pragma unroll
            for (int u = 0; u < 8; u++) ar[u] = As[kk][ty * 8 + u];
            #pragma unroll
            for (int u = 0; u < 8; u++) br[u] = Bs[kk][tx * 8 + u];
            #pragma unroll
            for (int i = 0; i < 8; i++)
                #pragma unroll
                for (int j = 0; j < 8; j++) acc[i][j] += ar[i] * br[j];
        }
        __syncthreads();
    }
    float* C = Cbase + (size_t)bg * QLEN * QLEN;
    const int mbase = by * 128 + ty * 8;
    const int nbase = bx * 128 + tx * 8;
    #pragma unroll
    for (int i = 0; i < 8; i++) {
        size_t roff = (size_t)(mbase + i) * QLEN + nbase;
        #pragma unroll
        for (int j0 = 0; j0 < 8; j0 += 4) {
            float4 o;
            o.x = acc[i][j0 + 0]; o.y = acc[i][j0 + 1];
            o.z = acc[i][j0 + 2]; o.w = acc[i][j0 + 3];
            *(float4*)(C + roff + j0) = o;
        }
    }
}

// ---------------- fused score + rel_shift + mask + softmax + PV -------------
__global__ void __launch_bounds__(512) attn_kernel(
    const float* __restrict__ AC, const float* __restrict__ BD,
    const float* __restrict__ masks, const float* __restrict__ mproj,
    const float* __restrict__ wheads, float* __restrict__ avec)
{
    extern __shared__ float S[];            // 32 * 1024
    __shared__ float invs[32];

    const int bh = blockIdx.x;
    const int b  = bh >> 4, h = bh & 15;
    const int g  = h >> 3;
    const int bg = b * 2 + g;
    const int i0 = blockIdx.y * 32;
    const int t  = threadIdx.x;
    const int warp = t >> 5, lane = t & 31;

    const float mp0 = mproj[0 * NHEAD + h];
    const float mp1 = mproj[1 * NHEAD + h];
    const float mp2 = mproj[2 * NHEAD + h];

    #pragma unroll
    for (int rr = 0; rr < 2; rr++) {
        const int r = warp * 2 + rr;
        const int i = i0 + r;
        const float* acrow = AC + ((size_t)bg * QLEN + i) * QLEN;
        const float* bdbase = BD + (size_t)bg * QLEN * QLEN;
        float mx = -1e30f;
        for (int j = lane; j < QLEN; j += 32) {
            float ac = acrow[j];
            unsigned s  = (unsigned)(i + 1) * 1024u + (unsigned)j;
            unsigned i2 = s / 1025u;
            unsigned j2 = s - i2 * 1025u;
            float bd = (j2 == 0u) ? 0.f : bdbase[(size_t)i2 * QLEN + (j2 - 1u)];
            const float* mrow = masks + ((size_t)i * QLEN + j) * 3;
            float mw = mrow[0] * mp0 + mrow[1] * mp1 + mrow[2] * mp2;
            float v = (ac + bd) * SCALE * mw;
            S[r * QLEN + j] = v;
            mx = fmaxf(mx, v);
        }
        #pragma unroll
        for (int o = 16; o > 0; o >>= 1)
            mx = fmaxf(mx, __shfl_xor_sync(0xffffffffu, mx, o));
        float sum = 0.f;
        for (int j = lane; j < QLEN; j += 32) {
            float e = __expf(S[r * QLEN + j] - mx);
            S[r * QLEN + j] = e;
            sum += e;
        }
        #pragma unroll
        for (int o = 16; o > 0; o >>= 1)
            sum += __shfl_xor_sync(0xffffffffu, sum, o);
        if (lane == 0) invs[r] = 1.f / sum;
    }
    __syncthreads();

    const int r  = t >> 4;
    const int d4 = t & 15;
    const int i  = i0 + r;
    const float* Vbase = wheads + (size_t)b * QKVOUT + 2 * QKD + h * 64 + d4 * 4;
    const float* Sr = S + r * QLEN;
    float4 acc = make_float4(0.f, 0.f, 0.f, 0.f);
    #pragma unroll 4
    for (int j = 0; j < QLEN; j++) {
        float p = Sr[j];
        float4 v = *(const float4*)(Vbase + (size_t)j * (BSZ * QKVOUT));
        acc.x += p * v.x; acc.y += p * v.y;
        acc.z += p * v.z; acc.w += p * v.w;
    }
    float is = invs[r];
    acc.x *= is; acc.y *= is; acc.z *= is; acc.w *= is;
    *(float4*)(avec + ((size_t)(i * BSZ + b) * NHEAD + h) * 64 + d4 * 4) = acc;
}

// ---------------- LayerNorm over rows of g_x --------------------------------
__global__ void __launch_bounds__(256) ln_kernel(
    const float* __restrict__ X, const float* __restrict__ gamma,
    const float* __restrict__ beta, float* __restrict__ out)
{
    const int row = blockIdx.x;
    const int t = threadIdx.x;
    const float4* x4 = (const float4*)(X + (size_t)row * DMODEL);
    float4 v = x4[t];
    float s  = v.x + v.y + v.z + v.w;
    float sq = v.x * v.x + v.y * v.y + v.z * v.z + v.w * v.w;
    #pragma unroll
    for (int o = 16; o > 0; o >>= 1) {
        s  += __shfl_xor_sync(0xffffffffu, s,  o);
        sq += __shfl_xor_sync(0xffffffffu, sq, o);
    }
    __shared__ float ssum[8], ssq[8];
    __shared__ float smu, srstd;
    if ((t & 31) == 0) { ssum[t >> 5] = s; ssq[t >> 5] = sq; }
    __syncthreads();
    if (t == 0) {
        float ts = 0.f, tq = 0.f;
        #pragma unroll
        for (int k = 0; k < 8; k++) { ts += ssum[k]; tq += ssq[k]; }
        float mu = ts * (1.f / DMODEL);
        float var = tq * (1.f / DMODEL) - mu * mu;
        smu = mu;
        srstd = rsqrtf(var + LN_EPS);
    }
    __syncthreads();
    float mu = smu, rstd = srstd;
    float4 gm = ((const float4*)gamma)[t];
    float4 bt = ((const float4*)beta)[t];
    float4 o;
    o.x = (v.x - mu) * rstd * gm.x + bt.x;
    o.y = (v.y - mu) * rstd * gm.y + bt.y;
    o.z = (v.z - mu) * rstd * gm.z + bt.z;
    o.w = (v.w - mu) * rstd * gm.w + bt.w;
    ((float4*)(out + (size_t)row * DMODEL))[t] = o;
}

// ---------------- launch ----------------------------------------------------
extern "C" void kernel_launch(void* const* d_in, const int* in_sizes, int n_in,
                              void* d_out, int out_size)
{
    const float* w     = (const float*)d_in[0];   // [1024,4,1024]
    const float* r     = (const float*)d_in[1];   // [1024,1024]
    const float* rwb   = (const float*)d_in[2];   // [2,64]
    const float* rrb   = (const float*)d_in[3];   // [2,64]
    const float* masks = (const float*)d_in[4];   // [1024,1024,3]
    const float* Wqkv  = (const float*)d_in[5];   // [1280,1024]
    const float* Wr    = (const float*)d_in[6];   // [128,1024]
    const float* mproj = (const float*)d_in[7];   // [3,16]
    const float* Wo    = (const float*)d_in[8];   // [1024,1024]
    const float* gamma = (const float*)d_in[9];   // [1024]
    const float* beta  = (const float*)d_in[10];  // [1024]
    float* out = (float*)d_out;

    float *wheads, *rkp, *acp, *bdp, *avp, *xp;
    cudaGetSymbolAddress((void**)&wheads, g_wheads);
    cudaGetSymbolAddress((void**)&rkp,    g_rk);
    cudaGetSymbolAddress((void**)&acp,    g_AC);
    cudaGetSymbolAddress((void**)&bdp,    g_BD);
    cudaGetSymbolAddress((void**)&avp,    g_avec);
    cudaGetSymbolAddress((void**)&xp,     g_x);

    __nv_bfloat16 *Ah, *Al, *Bh, *Bl;
    cudaGetSymbolAddress((void**)&Ah, g_bfA_hi);
    cudaGetSymbolAddress((void**)&Al, g_bfA_lo);
    cudaGetSymbolAddress((void**)&Bh, g_bfB_hi);
    cudaGetSymbolAddress((void**)&Bl, g_bfB_lo);

    cudaFuncSetAttribute(attn_kernel,
                         cudaFuncAttributeMaxDynamicSharedMemorySize,
                         32 * QLEN * (int)sizeof(float));

    // 1) w_heads = w @ W_qkv^T  (HMMA split-bf16)
    cvt_split<<<(MROWS * DMODEL) / 1024, 256>>>(w, Ah, Al, MROWS * DMODEL);
    cvt_split<<<(QKVOUT * DMODEL) / 1024, 256>>>(Wqkv, Bh, Bl, QKVOUT * DMODEL);
    mma_gemm<<<dim3(QKVOUT / 128, MROWS / 128), 256>>>(
        Ah, Al, Bh, Bl, nullptr, wheads, QKVOUT, DMODEL);

    // 2) r_head_k = r @ W_r^T
    cvt_split<<<(QLEN * DMODEL) / 1024, 256>>>(r, Ah, Al, QLEN * DMODEL);
    cvt_split<<<(QKD * DMODEL) / 1024, 256>>>(Wr, Bh, Bl, QKD * DMODEL);
    mma_gemm<<<dim3(QKD / 128, QLEN / 128), 256>>>(
        Ah, Al, Bh, Bl, nullptr, rkp, QKD, DMODEL);

    // 3) AC, BD (pre-shift)
    acbd_kernel<<<dim3(8, 8, BSZ * GHEADS), 256>>>(wheads, rkp, rwb, acp, 0);
    acbd_kernel<<<dim3(8, 8, BSZ * GHEADS), 256>>>(wheads, rkp, rrb, bdp, 1);

    // 4) fused rel_shift + mask + softmax + P@V
    attn_kernel<<<dim3(64, 32), 512, 32 * QLEN * sizeof(float)>>>(
        acp, bdp, masks, mproj, wheads, avp);

    // 5) x = attn_vec @ W_o^T + w  (HMMA split-bf16, fused residual)
    cvt_split<<<(MROWS * DMODEL) / 1024, 256>>>(avp, Ah, Al, MROWS * DMODEL);
    cvt_split<<<(DMODEL * DMODEL) / 1024, 256>>>(Wo, Bh, Bl, DMODEL * DMODEL);
    mma_gemm<<<dim3(DMODEL / 128, MROWS / 128), 256>>>(
        Ah, Al, Bh, Bl, w, xp, DMODEL, DMODEL);

    // 6) LayerNorm -> out
    ln_kernel<<<MROWS, 256>>>(xp, gamma, beta, out);
}